// round 11
// baseline (speedup 1.0000x reference)
#include <cuda_runtime.h>
#include <cuda_fp16.h>
#include <cstdint>

typedef unsigned long long u64;
typedef unsigned int u32;

#define PITCH   68
#define ROWS    64
#define NTHR    256
#define DIMC    128
#define KC      1024
#define SDIM    256
#define XD      8
#define BTOT    262144

#define VROWS   64
#define VTHR    256
#define NCHUNK  8
#define CHN     128
#define CAND_MAX 32
#define APW     68
#define DOTSCALE 0.0009765625f   // 2^-10 exact
#define CHBYTES 34816

#define DROWS   128
#define DTHR    512

// ---------------- scratch globals ----------------
__device__ float   g_cnorm[KC];
__device__ __half  g_ch16[KC * DIMC];       // fp16(codebook * 1024)
__device__ float   g_ze[(size_t)BTOT * DIMC];
__device__ float   g_znorm[BTOT];
__device__ float   g_zabs[BTOT];
__device__ int     g_idx[BTOT];
__device__ __half  g_w1h[128 * 384];        // dec w1^T * 64 (hi)
__device__ __half  g_w1l[128 * 384];        // (lo)
__device__ __half  g_w2h[128 * 128];
__device__ __half  g_w2l[128 * 128];

// ---------------- prep ----------------
__global__ void vq_prep(const float* __restrict__ cb) {
    int j = blockIdx.x;
    int d = threadIdx.x;
    float v = cb[j * DIMC + d];
    g_ch16[j * DIMC + d] = __float2half_rn(v * 1024.0f);
    __shared__ float red[DIMC];
    red[d] = v * v;
    __syncthreads();
    #pragma unroll
    for (int s = 64; s > 0; s >>= 1) {
        if (d < s) red[d] += red[d + s];
        __syncthreads();
    }
    if (d == 0) g_cnorm[j] = red[0];
}

// transpose + fp16-split decoder weights (scaled x64)
__global__ void dec_prep(const float* __restrict__ dw1, const float* __restrict__ dw2) {
    int i = blockIdx.x * 256 + threadIdx.x;
    if (i < 128 * 384) {
        int n = i / 384, k = i % 384;
        float v = dw1[k * 128 + n] * 64.0f;
        __half h = __float2half_rn(v);
        g_w1h[i] = h;
        g_w1l[i] = __float2half_rn(v - __half2float(h));
    } else if (i < 128 * 384 + 128 * 128) {
        int j = i - 128 * 384;
        int n = j / 128, k = j % 128;
        float v = dw2[k * 128 + n] * 64.0f;
        __half h = __float2half_rn(v);
        g_w2h[j] = h;
        g_w2l[j] = __float2half_rn(v - __half2float(h));
    }
}

// ---------------- packed f32x2 helpers ----------------
__device__ __forceinline__ u64 dup2(float w) {
    u64 r; unsigned u = __float_as_uint(w);
    asm("mov.b64 %0, {%1, %1};" : "=l"(r) : "r"(u));
    return r;
}
__device__ __forceinline__ void ffma2(u64& d, u64 a, u64 b) {
    asm("fma.rn.f32x2 %0, %1, %2, %0;" : "+l"(d) : "l"(a), "l"(b));
}
__device__ __forceinline__ float2 unpk(u64 v) {
    unsigned lo, hi;
    asm("mov.b64 {%0, %1}, %2;" : "=r"(lo), "=r"(hi) : "l"(v));
    return make_float2(__uint_as_float(lo), __uint_as_float(hi));
}

// ---------------- fp32 gemm (accumulate + store split) ----------------
__device__ __forceinline__ void gemm_accum(
    const float* __restrict__ inS, int Kdim,
    const float* __restrict__ W, u64 (&acc)[4][4], int warp, int lane)
{
    const int r0 = warp * 8;
    const int c0 = lane * 4;
    #pragma unroll 4
    for (int k = 0; k < Kdim; k++) {
        const ulonglong2 aA = *(const ulonglong2*)(inS + k * PITCH + r0);
        const ulonglong2 aB = *(const ulonglong2*)(inS + k * PITCH + r0 + 4);
        const float4 w = *(const float4*)(W + (size_t)k * DIMC + c0);
        const u64 wd[4] = {dup2(w.x), dup2(w.y), dup2(w.z), dup2(w.w)};
        const u64 av[4] = {aA.x, aA.y, aB.x, aB.y};
        #pragma unroll
        for (int i = 0; i < 4; i++) {
            ffma2(acc[i][0], av[i], wd[0]);
            ffma2(acc[i][1], av[i], wd[1]);
            ffma2(acc[i][2], av[i], wd[2]);
            ffma2(acc[i][3], av[i], wd[3]);
        }
    }
}
__device__ __forceinline__ void gemm_store(
    u64 (&acc)[4][4], const float* __restrict__ bias,
    float* __restrict__ outS, bool relu, int warp, int lane)
{
    const int r0 = warp * 8;
    const int c0 = lane * 4;
    const float4 b = *(const float4*)(bias + c0);
    const float bv[4] = {b.x, b.y, b.z, b.w};
    #pragma unroll
    for (int j = 0; j < 4; j++) {
        float o[8];
        #pragma unroll
        for (int i = 0; i < 4; i++) {
            float2 p = unpk(acc[i][j]);
            float v0 = p.x + bv[j];
            float v1 = p.y + bv[j];
            o[2 * i]     = relu ? fmaxf(v0, 0.f) : v0;
            o[2 * i + 1] = relu ? fmaxf(v1, 0.f) : v1;
        }
        *(float4*)(outS + (c0 + j) * PITCH + r0)     = make_float4(o[0], o[1], o[2], o[3]);
        *(float4*)(outS + (c0 + j) * PITCH + r0 + 4) = make_float4(o[4], o[5], o[6], o[7]);
    }
}
#define ACC_ZERO(acc) do { _Pragma("unroll") \
    for (int _i = 0; _i < 4; _i++) { acc[_i][0]=0; acc[_i][1]=0; acc[_i][2]=0; acc[_i][3]=0; } } while (0)

// ---------------- encoder (R7: k-chunked staging, 3 CTAs/SM) ----------------
__global__ void __launch_bounds__(NTHR, 3) enc_kernel(
    const float* __restrict__ state, const float* __restrict__ x,
    const float* __restrict__ ew1, const float* __restrict__ eb1,
    const float* __restrict__ ew2, const float* __restrict__ eb2,
    const float* __restrict__ ew3, const float* __restrict__ eb3,
    float* __restrict__ out, int nrows)
{
    extern __shared__ float sm[];
    float* X  = sm;                      // [136][PITCH] staging / h2
    float* hA = sm + 136 * PITCH;        // [128][PITCH]

    const int tid  = threadIdx.x;
    const int warp = tid >> 5, lane = tid & 31;
    const int rbase = blockIdx.x * ROWS;

    u64 acc[4][4];
    ACC_ZERO(acc);

    for (int e = tid; e < ROWS * 128; e += NTHR) {
        int r = e >> 7, k = e & 127;
        X[k * PITCH + r] = state[(size_t)(rbase + r) * SDIM + k];
    }
    __syncthreads();
    gemm_accum(X, 128, ew1, acc, warp, lane);
    __syncthreads();

    for (int e = tid; e < ROWS * 128; e += NTHR) {
        int r = e >> 7, k = e & 127;
        X[k * PITCH + r] = state[(size_t)(rbase + r) * SDIM + 128 + k];
    }
    for (int e = tid; e < ROWS * XD; e += NTHR) {
        int r = e >> 3, k = e & 7;
        X[(128 + k) * PITCH + r] = x[(size_t)(rbase + r) * XD + k];
    }
    __syncthreads();
    gemm_accum(X, 136, ew1 + (size_t)128 * DIMC, acc, warp, lane);
    gemm_store(acc, eb1, hA, true, warp, lane);
    __syncthreads();

    ACC_ZERO(acc);
    gemm_accum(hA, DIMC, ew2, acc, warp, lane);
    gemm_store(acc, eb2, X, true, warp, lane);
    __syncthreads();

    ACC_ZERO(acc);
    gemm_accum(X, DIMC, ew3, acc, warp, lane);
    gemm_store(acc, eb3, hA, false, warp, lane);   // z_e -> hA
    __syncthreads();

    if (tid < ROWS) {
        float s = 0.f, a = 0.f;
        #pragma unroll 4
        for (int d = 0; d < DIMC; d++) {
            float z = hA[d * PITCH + tid];
            s = fmaf(z, z, s);
            a += fabsf(z);
        }
        g_znorm[rbase + tid] = s;
        g_zabs[rbase + tid]  = a;
    }

    const size_t B = (size_t)nrows;
    float* out_ze = out + B * XD;
    for (int e = tid; e < ROWS * DIMC; e += NTHR) {
        int r = e >> 7, d = e & 127;
        float z = hA[d * PITCH + r];
        out_ze[(size_t)(rbase + r) * DIMC + d] = z;
        g_ze[(size_t)(rbase + r) * DIMC + d]   = z;
    }
}

// ---------------- fp16 mma + ldmatrix helpers ----------------
__device__ __forceinline__ void mma16816(float* d, u32 a0, u32 a1, u32 a2, u32 a3,
                                         u32 b0, u32 b1) {
    asm volatile(
        "mma.sync.aligned.m16n8k16.row.col.f32.f16.f16.f32 "
        "{%0,%1,%2,%3}, {%4,%5,%6,%7}, {%8,%9}, {%0,%1,%2,%3};"
        : "+f"(d[0]), "+f"(d[1]), "+f"(d[2]), "+f"(d[3])
        : "r"(a0), "r"(a1), "r"(a2), "r"(a3), "r"(b0), "r"(b1));
}
__device__ __forceinline__ void ldsm_x4(u32& r0, u32& r1, u32& r2, u32& r3, u32 addr) {
    asm volatile("ldmatrix.sync.aligned.m8n8.x4.shared.b16 {%0,%1,%2,%3}, [%4];"
                 : "=r"(r0), "=r"(r1), "=r"(r2), "=r"(r3) : "r"(addr));
}
__device__ __forceinline__ void ldsm_x2(u32& r0, u32& r1, u32 addr) {
    asm volatile("ldmatrix.sync.aligned.m8n8.x2.shared.b16 {%0,%1}, [%2];"
                 : "=r"(r0), "=r"(r1) : "r"(addr));
}
__device__ __forceinline__ u32 smem_u32(const void* p) {
    u32 a;
    asm("{ .reg .u64 t; cvta.to.shared.u64 t, %1; cvt.u32.u64 %0, t; }" : "=r"(a) : "l"(p));
    return a;
}
__device__ __forceinline__ u32 fmap(float f) {
    u32 u = __float_as_uint(f);
    return (u & 0x80000000u) ? ~u : (u | 0x80000000u);
}
__device__ __forceinline__ float finv(u32 m) {
    u32 u = (m & 0x80000000u) ? (m ^ 0x80000000u) : ~m;
    return __uint_as_float(u);
}

// ---------------- VQ kernel (fp16 screen; 1 barrier/chunk; 2 CTAs/SM) --------
// smem: 0 finalS u64[64] | 512 margS f32[64] | 768 bestU u32[64]
//       1024 cntS u32[64] | 1280 candS u32[64*32] (8192) | 9472 zhS u32[64*68]
//       26880 chB0 (34816) | 61696 chB1 (34816) | end 96512
#define VQ_SMEM 96512

__global__ void __launch_bounds__(VTHR, 2) vq_kernel(
    const float* __restrict__ cb, float* __restrict__ out, int nrows)
{
    extern __shared__ char smc[];
    u64*   finalS = (u64*)(smc);
    float* margS  = (float*)(smc + 512);
    u32*   bestU  = (u32*)(smc + 768);
    u32*   cntS   = (u32*)(smc + 1024);
    u32*   candS  = (u32*)(smc + 1280);
    u32*   zhS    = (u32*)(smc + 9472);
    u32*   chB    = (u32*)(smc + 26880);   // two buffers of 34816B each

    const int tid  = threadIdx.x;
    const int wid  = tid >> 5, lane = tid & 31;
    const int g    = lane >> 2, tg = lane & 3;
    const int rbase = blockIdx.x * VROWS;

    // 8 warps = 2 M-groups (32 rows) x 4 N-quarters (32 cols)
    const int mbase = (wid >> 2) * 32;
    const int nq    = (wid & 3) * 32;

    for (int i = tid; i < VROWS; i += VTHR) {
        bestU[i]  = 0xFFFFFFFFu;
        finalS[i] = ~0ull;
        cntS[i]   = 0u;
        margS[i]  = g_zabs[rbase + i] * 4.0e-6f + 4.0e-6f;
    }

    // stage A: zh = fp16(z_e)
    for (int i = tid; i < VROWS * 64; i += VTHR) {
        int r = i >> 6, c = i & 63;
        float2 z = *(const float2*)(g_ze + (size_t)(rbase + r) * DIMC + c * 2);
        __half2 hp(__float2half_rn(z.x), __float2half_rn(z.y));
        zhS[r * APW + c] = *(u32*)&hp;
    }

    // stage B chunk 0 into buffer 0
    {
        const uint4* src = (const uint4*)(g_ch16);
        #pragma unroll
        for (int t = 0; t < 8; t++) {
            int i = t * VTHR + tid;
            uint4 v = src[i];
            *(uint4*)(chB + (i >> 4) * APW + (i & 15) * 4) = v;
        }
    }
    __syncthreads();

    const int r0 = mbase + g;
    const float mg0 = margS[r0], mg1 = margS[r0 + 8];
    const float mg2 = margS[r0 + 16], mg3 = margS[r0 + 24];

    // ldmatrix lane addresses (byte offsets into shared space)
    const u32 zhBase = smem_u32(zhS);
    const u32 chBase = smem_u32(chB);
    const u32 aAddr0 = zhBase + (((mbase      + (lane & 15)) * APW) + (lane >> 4) * 4) * 4;
    const u32 aAddr1 = zhBase + (((mbase + 16 + (lane & 15)) * APW) + (lane >> 4) * 4) * 4;
    const u32 bAddr  = chBase + (((nq + (lane & 7)) * APW) + ((lane >> 3) & 1) * 4) * 4;

    float dacc[2][4][4];

    for (int q = 0; q < NCHUNK; q++) {
        const u32 bufOff = (u32)(q & 1) * CHBYTES;
        u32* chN = chB + (((q + 1) & 1) * (CHBYTES / 4));

        #pragma unroll
        for (int mt = 0; mt < 2; mt++)
            #pragma unroll
            for (int nt = 0; nt < 4; nt++) {
                dacc[mt][nt][0] = 0.f; dacc[mt][nt][1] = 0.f;
                dacc[mt][nt][2] = 0.f; dacc[mt][nt][3] = 0.f;
            }

        // ---- MMA on current buffer ----
        #pragma unroll
        for (int kt = 0; kt < 8; kt++) {
            const u32 koff = kt * 32;
            u32 a0[4], a1[4];
            ldsm_x4(a0[0], a0[1], a0[2], a0[3], aAddr0 + koff);
            ldsm_x4(a1[0], a1[1], a1[2], a1[3], aAddr1 + koff);
            #pragma unroll
            for (int nt = 0; nt < 4; nt++) {
                u32 b0, b1;
                ldsm_x2(b0, b1, bAddr + bufOff + nt * (8 * APW * 4) + koff);
                mma16816(dacc[0][nt], a0[0], a0[1], a0[2], a0[3], b0, b1);
                mma16816(dacc[1][nt], a1[0], a1[1], a1[2], a1[3], b0, b1);
            }
        }

        // ---- stage next chunk into the other buffer (no hazard: idle buffer) ----
        if (q < NCHUNK - 1) {
            const uint4* src = (const uint4*)(g_ch16 + (size_t)(q + 1) * CHN * DIMC);
            #pragma unroll
            for (int t = 0; t < 8; t++) {
                int i = t * VTHR + tid;
                uint4 v = src[i];
                *(uint4*)(chN + (i >> 4) * APW + (i & 15) * 4) = v;
            }
        }

        // ---- epilogue: scores + running min (threshold from own atomicMin) ----
        u32 mn0 = ~0u, mn1 = ~0u, mn2 = ~0u, mn3 = ~0u;
        #pragma unroll
        for (int mt = 0; mt < 2; mt++)
            #pragma unroll
            for (int nt = 0; nt < 4; nt++) {
                const int jb = q * CHN + nq + nt * 8 + 2 * tg;
                const float cn0 = __ldg(g_cnorm + jb);
                const float cn1 = __ldg(g_cnorm + jb + 1);
                float* d = dacc[mt][nt];
                float s0 = fmaf(d[0], -2.0f * DOTSCALE, cn0);
                float s1 = fmaf(d[1], -2.0f * DOTSCALE, cn1);
                float s2 = fmaf(d[2], -2.0f * DOTSCALE, cn0);
                float s3 = fmaf(d[3], -2.0f * DOTSCALE, cn1);
                d[0] = s0; d[1] = s1; d[2] = s2; d[3] = s3;
                u32 ma = min(fmap(s0), fmap(s1));
                u32 mb = min(fmap(s2), fmap(s3));
                if (mt == 0) { mn0 = min(mn0, ma); mn1 = min(mn1, mb); }
                else         { mn2 = min(mn2, ma); mn3 = min(mn3, mb); }
            }
        u32 o0 = atomicMin(&bestU[r0],      mn0);
        u32 o1 = atomicMin(&bestU[r0 + 8],  mn1);
        u32 o2 = atomicMin(&bestU[r0 + 16], mn2);
        u32 o3 = atomicMin(&bestU[r0 + 24], mn3);
        const float t0 = finv(min(o0, mn0)) + mg0;     // >= global-min thr -> superset
        const float t1 = finv(min(o1, mn1)) + mg1;
        const float t2 = finv(min(o2, mn2)) + mg2;
        const float t3 = finv(min(o3, mn3)) + mg3;

        #pragma unroll
        for (int mt = 0; mt < 2; mt++) {
            const int rA = r0 + mt * 16, rB = rA + 8;
            const float tA = mt ? t2 : t0;
            const float tB = mt ? t3 : t1;
            #pragma unroll
            for (int nt = 0; nt < 4; nt++) {
                const int jb = q * CHN + nq + nt * 8 + 2 * tg;
                const float* d = dacc[mt][nt];
                if (d[0] <= tA) {
                    u32 p = atomicAdd(&cntS[rA], 1u);
                    if (p < CAND_MAX) candS[rA * CAND_MAX + p] = (u32)jb;
                }
                if (d[1] <= tA) {
                    u32 p = atomicAdd(&cntS[rA], 1u);
                    if (p < CAND_MAX) candS[rA * CAND_MAX + p] = (u32)(jb + 1);
                }
                if (d[2] <= tB) {
                    u32 p = atomicAdd(&cntS[rB], 1u);
                    if (p < CAND_MAX) candS[rB * CAND_MAX + p] = (u32)jb;
                }
                if (d[3] <= tB) {
                    u32 p = atomicAdd(&cntS[rB], 1u);
                    if (p < CAND_MAX) candS[rB * CAND_MAX + p] = (u32)(jb + 1);
                }
            }
        }
        __syncthreads();   // next buffer staged by all; current buffer reads done
    }

    // exact fp32 refine (reference order); full-scan fallback on overflow
    {
        const int rr = tid >> 2, c4 = tid & 3;
        const float zn = g_znorm[rbase + rr];
        const float* zp = g_ze + (size_t)(rbase + rr) * DIMC;
        int cnt = (int)cntS[rr];
        if (cnt <= CAND_MAX) {
            for (int c = c4; c < cnt; c += 4) {
                int j = (int)candS[rr * CAND_MAX + c];
                const float* cp = cb + (size_t)j * DIMC;
                float dot = 0.f;
                #pragma unroll 8
                for (int d = 0; d < DIMC; d++) dot = fmaf(zp[d], cp[d], dot);
                float dvv = (zn - 2.0f * dot) + __ldg(g_cnorm + j);
                u64 key = ((u64)fmap(dvv) << 32) | (u32)j;
                atomicMin(&finalS[rr], key);
            }
        } else {
            for (int j = c4; j < KC; j += 4) {
                const float* cp = cb + (size_t)j * DIMC;
                float dot = 0.f;
                #pragma unroll 8
                for (int d = 0; d < DIMC; d++) dot = fmaf(zp[d], cp[d], dot);
                float dvv = (zn - 2.0f * dot) + __ldg(g_cnorm + j);
                u64 key = ((u64)fmap(dvv) << 32) | (u32)j;
                atomicMin(&finalS[rr], key);
            }
        }
    }
    __syncthreads();

    if (tid < VROWS) {
        int idx = (int)(finalS[tid] & 0xFFFFFFFFull);
        g_idx[rbase + tid] = idx;
        float* out_id = out + (size_t)nrows * XD + (size_t)nrows * DIMC * 2;
        out_id[rbase + tid] = (float)idx;
    }
}

// ---------------- decoder (fp16 2-term split tensor cores) -------------------
// smem: xh [128][APW]u32 @0 | xl @34816 | wh @69632 | wl @104448 | end 139264
// h2 fp32 [128 col][132 row pitch] aliases @69632
#define DEC_SMEM 139264

__global__ void __launch_bounds__(DTHR, 1) dec_kernel(
    const float* __restrict__ state, const float* __restrict__ cb,
    const float* __restrict__ db1, const float* __restrict__ db2,
    const float* __restrict__ dw3, const float* __restrict__ db3,
    float* __restrict__ out, int nrows)
{
    extern __shared__ char smc[];
    u32* xhS = (u32*)(smc);
    u32* xlS = (u32*)(smc + 34816);
    u32* whS = (u32*)(smc + 69632);
    u32* wlS = (u32*)(smc + 104448);
    float* h2S = (float*)(smc + 69632);     // alias over whS/wlS

    const int tid  = threadIdx.x;
    const int wid  = tid >> 5, lane = tid & 31;
    const int g    = lane >> 2, tg = lane & 3;
    const int rbase = blockIdx.x * DROWS;

    const int mbase = (wid >> 2) * 32;
    const int nq    = (wid & 3) * 32;

    const size_t B = (size_t)nrows;
    float* out_xt = out;
    float* out_zq = out + B * XD + B * (size_t)DIMC;

    float dacc[2][4][4];
    #pragma unroll
    for (int mt = 0; mt < 2; mt++)
        #pragma unroll
        for (int nt = 0; nt < 4; nt++) {
            dacc[mt][nt][0] = 0.f; dacc[mt][nt][1] = 0.f;
            dacc[mt][nt][2] = 0.f; dacc[mt][nt][3] = 0.f;
        }

    // ---- GEMM1: K=384 in 3 chunks of 128 ----
    for (int ch = 0; ch < 3; ch++) {
        if (ch < 2) {
            for (int i = tid; i < DROWS * 64; i += DTHR) {
                int r = i >> 6, cw = i & 63;
                float2 v = *(const float2*)(state + (size_t)(rbase + r) * SDIM + ch * 128 + 2 * cw);
                float v0 = v.x * 16.0f, v1 = v.y * 16.0f;
                __half h0 = __float2half_rn(v0), h1 = __float2half_rn(v1);
                __half l0 = __float2half_rn(v0 - __half2float(h0));
                __half l1 = __float2half_rn(v1 - __half2float(h1));
                __half2 hp(h0, h1), lp(l0, l1);
                xhS[r * APW + cw] = *(u32*)&hp;
                xlS[r * APW + cw] = *(u32*)&lp;
            }
        } else {
            for (int i = tid; i < DROWS * 64; i += DTHR) {
                int r = i >> 6, cw = i & 63;
                int d = 2 * cw;
                float2 z = *(const float2*)(g_ze + (size_t)(rbase + r) * DIMC + d);
                int idx = g_idx[rbase + r];
                float2 q = *(const float2*)(cb + (size_t)idx * DIMC + d);
                *(float2*)(out_zq + (size_t)(rbase + r) * DIMC + d) = q;
                float v0 = (z.x + (q.x - z.x)) * 16.0f;
                float v1 = (z.y + (q.y - z.y)) * 16.0f;
                __half h0 = __float2half_rn(v0), h1 = __float2half_rn(v1);
                __half l0 = __float2half_rn(v0 - __half2float(h0));
                __half l1 = __float2half_rn(v1 - __half2float(h1));
                __half2 hp(h0, h1), lp(l0, l1);
                xhS[r * APW + cw] = *(u32*)&hp;
                xlS[r * APW + cw] = *(u32*)&lp;
            }
        }
        {
            const u32* srcH = (const u32*)g_w1h;
            const u32* srcL = (const u32*)g_w1l;
            for (int i = tid; i < 128 * 64; i += DTHR) {
                int n = i >> 6, cw = i & 63;
                int woff = n * 192 + ch * 64 + cw;
                whS[n * APW + cw] = srcH[woff];
                wlS[n * APW + cw] = srcL[woff];
            }
        }
        __syncthreads();

        #pragma unroll
        for (int kt = 0; kt < 8; kt++) {
            const int ka = kt * 8 + tg;
            u32 ah[2][4], al[2][4];
            #pragma unroll
            for (int mt = 0; mt < 2; mt++) {
                const int rb = (mbase + mt * 16 + g) * APW;
                ah[mt][0] = xhS[rb + ka];
                ah[mt][1] = xhS[rb + 8 * APW + ka];
                ah[mt][2] = xhS[rb + ka + 4];
                ah[mt][3] = xhS[rb + 8 * APW + ka + 4];
                al[mt][0] = xlS[rb + ka];
                al[mt][1] = xlS[rb + 8 * APW + ka];
                al[mt][2] = xlS[rb + ka + 4];
                al[mt][3] = xlS[rb + 8 * APW + ka + 4];
            }
            #pragma unroll
            for (int nt = 0; nt < 4; nt++) {
                const int w = (nq + nt * 8 + g) * APW + ka;
                const u32 bh0 = whS[w], bh1 = whS[w + 4];
                const u32 bl0 = wlS[w], bl1 = wlS[w + 4];
                #pragma unroll
                for (int mt = 0; mt < 2; mt++) {
                    mma16816(dacc[mt][nt], ah[mt][0], ah[mt][1], ah[mt][2], ah[mt][3], bh0, bh1);
                    mma16816(dacc[mt][nt], al[mt][0], al[mt][1], al[mt][2], al[mt][3], bh0, bh1);
                    mma16816(dacc[mt][nt], ah[mt][0], ah[mt][1], ah[mt][2], ah[mt][3], bl0, bl1);
                }
            }
        }
        __syncthreads();
    }

    // ---- GEMM1 epilogue: h1 = relu(acc/1024 + b1); restage (x16 split) ----
    #pragma unroll
    for (int mt = 0; mt < 2; mt++) {
        const int rA = mbase + mt * 16 + g, rB = rA + 8;
        #pragma unroll
        for (int nt = 0; nt < 4; nt++) {
            const int jb = nq + nt * 8 + 2 * tg;
            const float b0v = __ldg(db1 + jb), b1v = __ldg(db1 + jb + 1);
            float* d = dacc[mt][nt];
            float s0 = fmaxf(fmaf(d[0], DOTSCALE, b0v), 0.f) * 16.0f;
            float s1 = fmaxf(fmaf(d[1], DOTSCALE, b1v), 0.f) * 16.0f;
            float s2 = fmaxf(fmaf(d[2], DOTSCALE, b0v), 0.f) * 16.0f;
            float s3 = fmaxf(fmaf(d[3], DOTSCALE, b1v), 0.f) * 16.0f;
            const int w = (nq >> 1) + nt * 4 + tg;
            __half h0 = __float2half_rn(s0), h1 = __float2half_rn(s1);
            __half l0 = __float2half_rn(s0 - __half2float(h0));
            __half l1 = __float2half_rn(s1 - __half2float(h1));
            __half2 hpA(h0, h1), lpA(l0, l1);
            xhS[rA * APW + w] = *(u32*)&hpA;
            xlS[rA * APW + w] = *(u32*)&lpA;
            __half h2 = __float2half_rn(s2), h3 = __float2half_rn(s3);
            __half l2 = __float2half_rn(s2 - __half2float(h2));
            __half l3 = __float2half_rn(s3 - __half2float(h3));
            __half2 hpB(h2, h3), lpB(l2, l3);
            xhS[rB * APW + w] = *(u32*)&hpB;
            xlS[rB * APW + w] = *(u32*)&lpB;
        }
    }
    {
        const u32* srcH = (const u32*)g_w2h;
        const u32* srcL = (const u32*)g_w2l;
        for (int i = tid; i < 128 * 64; i += DTHR) {
            int n = i >> 6, cw = i & 63;
            whS[n * APW + cw] = srcH[n * 64 + cw];
            wlS[n * APW + cw] = srcL[n * 64 + cw];
        }
    }
    __syncthreads();

    // ---- GEMM2: K=128 ----
    #pragma unroll
    for (int mt = 0; mt < 2; mt++)
        #pragma unroll
        for (int nt = 0; nt < 4; nt++) {
            dacc[mt][nt][0] = 0.f; dacc[mt][nt][1] = 0.f;
            dacc[mt][nt][2] = 0.f; dacc[mt][nt][3] = 0.f;
        }
    #pragma unroll
    for (int kt = 0; kt < 8; kt++) {
        const int ka = kt * 8 + tg;
        u32 ah[2][4], al[2][4];
        #pragma unroll
        for (int mt = 0; mt < 2; mt++) {
            const int rb = (mbase + mt * 16 + g) * APW;
            ah[mt][0] = xhS[rb + ka];
            ah[mt][1] = xhS[rb + 8 * APW + ka];
            ah[mt][2] = xhS[rb + ka + 4];
            ah[mt][3] = xhS[rb + 8 * APW + ka + 4];
            al[mt][0] = xlS[rb + ka];
            al[mt][1] = xlS[rb + 8 * APW + ka];
            al[mt][2] = xlS[rb + ka + 4];
            al[mt][3] = xlS[rb + 8 * APW + ka + 4];
        }
        #pragma unroll
        for (int nt = 0; nt < 4; nt++) {
            const int w = (nq + nt * 8 + g) * APW + ka;
            const u32 bh0 = whS[w], bh1 = whS[w + 4];
            const u32 bl0 = wlS[w], bl1 = wlS[w + 4];
            #pragma unroll
            for (int mt = 0; mt < 2; mt++) {
                mma16816(dacc[mt][nt], ah[mt][0], ah[mt][1], ah[mt][2], ah[mt][3], bh0, bh1);
                mma16816(dacc[mt][nt], al[mt][0], al[mt][1], al[mt][2], al[mt][3], bh0, bh1);
                mma16816(dacc[mt][nt], ah[mt][0], ah[mt][1], ah[mt][2], ah[mt][3], bl0, bl1);
            }
        }
    }
    __syncthreads();   // wh/wl reads done before h2 alias-write

    // ---- GEMM2 epilogue: h2 fp32 -> smem [col][row pitch 132] ----
    #pragma unroll
    for (int mt = 0; mt < 2; mt++) {
        const int rA = mbase + mt * 16 + g, rB = rA + 8;
        #pragma unroll
        for (int nt = 0; nt < 4; nt++) {
            const int jb = nq + nt * 8 + 2 * tg;
            const float b0v = __ldg(db2 + jb), b1v = __ldg(db2 + jb + 1);
            float* d = dacc[mt][nt];
            h2S[jb * 132 + rA]       = fmaxf(fmaf(d[0], DOTSCALE, b0v), 0.f);
            h2S[(jb + 1) * 132 + rA] = fmaxf(fmaf(d[1], DOTSCALE, b1v), 0.f);
            h2S[jb * 132 + rB]       = fmaxf(fmaf(d[2], DOTSCALE, b0v), 0.f);
            h2S[(jb + 1) * 132 + rB] = fmaxf(fmaf(d[3], DOTSCALE, b1v), 0.f);
        }
    }
    __syncthreads();

    // ---- final layer: fp32 scalar, 8 cols ----
    {
        int r = tid & 127;
        int c = (tid >> 7) * 2;
        float a0 = 0.f, a1 = 0.f;
        #pragma unroll 4
        for (int d = 0; d < DIMC; d++) {
            float h = h2S[d * 132 + r];
            a0 = fmaf(h, dw3[d * XD + c],     a0);
            a1 = fmaf(h, dw3[d * XD + c + 1], a1);
        }
        out_xt[(size_t)(rbase + r) * XD + c]     = a0 + db3[c];
        out_xt[(size_t)(rbase + r) * XD + c + 1] = a1 + db3[c + 1];
    }
}

// ---------------- launch ----------------
extern "C" void kernel_launch(void* const* d_in, const int* in_sizes, int n_in,
                              void* d_out, int out_size) {
    const float* state = (const float*)d_in[0];
    const float* x     = (const float*)d_in[1];
    const float* cb    = (const float*)d_in[2];
    const float* ew1   = (const float*)d_in[3];
    const float* eb1   = (const float*)d_in[4];
    const float* ew2   = (const float*)d_in[5];
    const float* eb2   = (const float*)d_in[6];
    const float* ew3   = (const float*)d_in[7];
    const float* eb3   = (const float*)d_in[8];
    const float* dw1   = (const float*)d_in[9];
    const float* db1   = (const float*)d_in[10];
    const float* dw2   = (const float*)d_in[11];
    const float* db2   = (const float*)d_in[12];
    const float* dw3   = (const float*)d_in[13];
    const float* db3   = (const float*)d_in[14];

    const int nrows = in_sizes[0] / SDIM;   // 262144

    size_t smemA = (size_t)(136 + 128) * PITCH * sizeof(float);   // 71808
    static bool attrs_set = false;
    if (!attrs_set) {
        cudaFuncSetAttribute((const void*)enc_kernel, cudaFuncAttributeMaxDynamicSharedMemorySize, (int)smemA);
        cudaFuncSetAttribute((const void*)vq_kernel,  cudaFuncAttributeMaxDynamicSharedMemorySize, VQ_SMEM);
        cudaFuncSetAttribute((const void*)dec_kernel, cudaFuncAttributeMaxDynamicSharedMemorySize, DEC_SMEM);
        attrs_set = true;
    }

    vq_prep<<<KC, DIMC>>>(cb);
    dec_prep<<<(128 * 384 + 128 * 128 + 255) / 256, 256>>>(dw1, dw2);
    enc_kernel<<<nrows / ROWS, NTHR, smemA>>>(state, x, ew1, eb1, ew2, eb2, ew3, eb3,
                                              (float*)d_out, nrows);
    vq_kernel<<<nrows / VROWS, VTHR, VQ_SMEM>>>(cb, (float*)d_out, nrows);
    dec_kernel<<<nrows / DROWS, DTHR, DEC_SMEM>>>(state, cb, db1, db2, dw3, db3,
                                                  (float*)d_out, nrows);
}

// round 12
// speedup vs baseline: 1.1960x; 1.1960x over previous
#include <cuda_runtime.h>
#include <cuda_fp16.h>
#include <cstdint>

typedef unsigned long long u64;
typedef unsigned int u32;

#define PITCH   68
#define ROWS    64
#define NTHR    256
#define DIMC    128
#define KC      1024
#define SDIM    256
#define XD      8
#define BTOT    262144

#define VROWS   64
#define VTHR    256
#define NCHUNK  8
#define CHN     128
#define CAND_MAX 32
#define APW     68
#define DOTSCALE 0.0009765625f   // 2^-10 exact
#define CHBYTES 34816

#define DROWS   128
#define DTHR    512

// ---------------- scratch globals ----------------
__device__ float   g_cnorm[KC];
__device__ __half  g_ch16[KC * DIMC];       // fp16(codebook * 1024)
__device__ float   g_ze[(size_t)BTOT * DIMC];
__device__ float   g_znorm[BTOT];
__device__ float   g_zabs[BTOT];
__device__ int     g_idx[BTOT];
__device__ __half  g_w1h[128 * 384];        // dec w1^T * 64 (hi)
__device__ __half  g_w1l[128 * 384];        // (lo)
__device__ __half  g_w2h[128 * 128];
__device__ __half  g_w2l[128 * 128];

// ---------------- prep ----------------
__global__ void vq_prep(const float* __restrict__ cb) {
    int j = blockIdx.x;
    int d = threadIdx.x;
    float v = cb[j * DIMC + d];
    g_ch16[j * DIMC + d] = __float2half_rn(v * 1024.0f);
    __shared__ float red[DIMC];
    red[d] = v * v;
    __syncthreads();
    #pragma unroll
    for (int s = 64; s > 0; s >>= 1) {
        if (d < s) red[d] += red[d + s];
        __syncthreads();
    }
    if (d == 0) g_cnorm[j] = red[0];
}

// transpose + fp16-split decoder weights (scaled x64)
__global__ void dec_prep(const float* __restrict__ dw1, const float* __restrict__ dw2) {
    int i = blockIdx.x * 256 + threadIdx.x;
    if (i < 128 * 384) {
        int n = i / 384, k = i % 384;
        float v = dw1[k * 128 + n] * 64.0f;
        __half h = __float2half_rn(v);
        g_w1h[i] = h;
        g_w1l[i] = __float2half_rn(v - __half2float(h));
    } else if (i < 128 * 384 + 128 * 128) {
        int j = i - 128 * 384;
        int n = j / 128, k = j % 128;
        float v = dw2[k * 128 + n] * 64.0f;
        __half h = __float2half_rn(v);
        g_w2h[j] = h;
        g_w2l[j] = __float2half_rn(v - __half2float(h));
    }
}

// ---------------- packed f32x2 helpers ----------------
__device__ __forceinline__ u64 dup2(float w) {
    u64 r; unsigned u = __float_as_uint(w);
    asm("mov.b64 %0, {%1, %1};" : "=l"(r) : "r"(u));
    return r;
}
__device__ __forceinline__ void ffma2(u64& d, u64 a, u64 b) {
    asm("fma.rn.f32x2 %0, %1, %2, %0;" : "+l"(d) : "l"(a), "l"(b));
}
__device__ __forceinline__ float2 unpk(u64 v) {
    unsigned lo, hi;
    asm("mov.b64 {%0, %1}, %2;" : "=r"(lo), "=r"(hi) : "l"(v));
    return make_float2(__uint_as_float(lo), __uint_as_float(hi));
}

// ---------------- fp32 gemm (accumulate + store split) ----------------
__device__ __forceinline__ void gemm_accum(
    const float* __restrict__ inS, int Kdim,
    const float* __restrict__ W, u64 (&acc)[4][4], int warp, int lane)
{
    const int r0 = warp * 8;
    const int c0 = lane * 4;
    #pragma unroll 4
    for (int k = 0; k < Kdim; k++) {
        const ulonglong2 aA = *(const ulonglong2*)(inS + k * PITCH + r0);
        const ulonglong2 aB = *(const ulonglong2*)(inS + k * PITCH + r0 + 4);
        const float4 w = *(const float4*)(W + (size_t)k * DIMC + c0);
        const u64 wd[4] = {dup2(w.x), dup2(w.y), dup2(w.z), dup2(w.w)};
        const u64 av[4] = {aA.x, aA.y, aB.x, aB.y};
        #pragma unroll
        for (int i = 0; i < 4; i++) {
            ffma2(acc[i][0], av[i], wd[0]);
            ffma2(acc[i][1], av[i], wd[1]);
            ffma2(acc[i][2], av[i], wd[2]);
            ffma2(acc[i][3], av[i], wd[3]);
        }
    }
}
__device__ __forceinline__ void gemm_store(
    u64 (&acc)[4][4], const float* __restrict__ bias,
    float* __restrict__ outS, bool relu, int warp, int lane)
{
    const int r0 = warp * 8;
    const int c0 = lane * 4;
    const float4 b = *(const float4*)(bias + c0);
    const float bv[4] = {b.x, b.y, b.z, b.w};
    #pragma unroll
    for (int j = 0; j < 4; j++) {
        float o[8];
        #pragma unroll
        for (int i = 0; i < 4; i++) {
            float2 p = unpk(acc[i][j]);
            float v0 = p.x + bv[j];
            float v1 = p.y + bv[j];
            o[2 * i]     = relu ? fmaxf(v0, 0.f) : v0;
            o[2 * i + 1] = relu ? fmaxf(v1, 0.f) : v1;
        }
        *(float4*)(outS + (c0 + j) * PITCH + r0)     = make_float4(o[0], o[1], o[2], o[3]);
        *(float4*)(outS + (c0 + j) * PITCH + r0 + 4) = make_float4(o[4], o[5], o[6], o[7]);
    }
}
#define ACC_ZERO(acc) do { _Pragma("unroll") \
    for (int _i = 0; _i < 4; _i++) { acc[_i][0]=0; acc[_i][1]=0; acc[_i][2]=0; acc[_i][3]=0; } } while (0)

// ---------------- encoder (R7: k-chunked staging, 3 CTAs/SM) ----------------
__global__ void __launch_bounds__(NTHR, 3) enc_kernel(
    const float* __restrict__ state, const float* __restrict__ x,
    const float* __restrict__ ew1, const float* __restrict__ eb1,
    const float* __restrict__ ew2, const float* __restrict__ eb2,
    const float* __restrict__ ew3, const float* __restrict__ eb3,
    float* __restrict__ out, int nrows)
{
    extern __shared__ float sm[];
    float* X  = sm;                      // [136][PITCH] staging / h2
    float* hA = sm + 136 * PITCH;        // [128][PITCH]

    const int tid  = threadIdx.x;
    const int warp = tid >> 5, lane = tid & 31;
    const int rbase = blockIdx.x * ROWS;

    u64 acc[4][4];
    ACC_ZERO(acc);

    for (int e = tid; e < ROWS * 128; e += NTHR) {
        int r = e >> 7, k = e & 127;
        X[k * PITCH + r] = state[(size_t)(rbase + r) * SDIM + k];
    }
    __syncthreads();
    gemm_accum(X, 128, ew1, acc, warp, lane);
    __syncthreads();

    for (int e = tid; e < ROWS * 128; e += NTHR) {
        int r = e >> 7, k = e & 127;
        X[k * PITCH + r] = state[(size_t)(rbase + r) * SDIM + 128 + k];
    }
    for (int e = tid; e < ROWS * XD; e += NTHR) {
        int r = e >> 3, k = e & 7;
        X[(128 + k) * PITCH + r] = x[(size_t)(rbase + r) * XD + k];
    }
    __syncthreads();
    gemm_accum(X, 136, ew1 + (size_t)128 * DIMC, acc, warp, lane);
    gemm_store(acc, eb1, hA, true, warp, lane);
    __syncthreads();

    ACC_ZERO(acc);
    gemm_accum(hA, DIMC, ew2, acc, warp, lane);
    gemm_store(acc, eb2, X, true, warp, lane);
    __syncthreads();

    ACC_ZERO(acc);
    gemm_accum(X, DIMC, ew3, acc, warp, lane);
    gemm_store(acc, eb3, hA, false, warp, lane);   // z_e -> hA
    __syncthreads();

    if (tid < ROWS) {
        float s = 0.f, a = 0.f;
        #pragma unroll 4
        for (int d = 0; d < DIMC; d++) {
            float z = hA[d * PITCH + tid];
            s = fmaf(z, z, s);
            a += fabsf(z);
        }
        g_znorm[rbase + tid] = s;
        g_zabs[rbase + tid]  = a;
    }

    const size_t B = (size_t)nrows;
    float* out_ze = out + B * XD;
    for (int e = tid; e < ROWS * DIMC; e += NTHR) {
        int r = e >> 7, d = e & 127;
        float z = hA[d * PITCH + r];
        out_ze[(size_t)(rbase + r) * DIMC + d] = z;
        g_ze[(size_t)(rbase + r) * DIMC + d]   = z;
    }
}

// ---------------- fp16 mma + cp.async helpers ----------------
__device__ __forceinline__ void mma16816(float* d, u32 a0, u32 a1, u32 a2, u32 a3,
                                         u32 b0, u32 b1) {
    asm volatile(
        "mma.sync.aligned.m16n8k16.row.col.f32.f16.f16.f32 "
        "{%0,%1,%2,%3}, {%4,%5,%6,%7}, {%8,%9}, {%0,%1,%2,%3};"
        : "+f"(d[0]), "+f"(d[1]), "+f"(d[2]), "+f"(d[3])
        : "r"(a0), "r"(a1), "r"(a2), "r"(a3), "r"(b0), "r"(b1));
}
__device__ __forceinline__ u32 smem_u32(const void* p) {
    u32 a;
    asm("{ .reg .u64 t; cvta.to.shared.u64 t, %1; cvt.u32.u64 %0, t; }" : "=r"(a) : "l"(p));
    return a;
}
__device__ __forceinline__ void cp16(u32 dst, const void* src) {
    asm volatile("cp.async.cg.shared.global [%0], [%1], 16;" :: "r"(dst), "l"(src) : "memory");
}
#define CP_COMMIT() asm volatile("cp.async.commit_group;" ::: "memory")
#define CP_WAIT0()  asm volatile("cp.async.wait_group 0;" ::: "memory")

__device__ __forceinline__ u32 fmap(float f) {
    u32 u = __float_as_uint(f);
    return (u & 0x80000000u) ? ~u : (u | 0x80000000u);
}
__device__ __forceinline__ float finv(u32 m) {
    u32 u = (m & 0x80000000u) ? (m ^ 0x80000000u) : ~m;
    return __uint_as_float(u);
}

// ---------------- VQ kernel (R10 + cp.async double buffer) -------------------
// smem: 0 finalS u64[64] | 512 margS f32[64] | 768 bestU u32[64]
//       1024 cntS u32[64] | 1280 candS u32[64*32] (8192) | 9472 zhS u32[64*68]
//       26880 chB0 (34816) | 61696 chB1 (34816) | end 96512
#define VQ_SMEM 96512

__global__ void __launch_bounds__(VTHR, 2) vq_kernel(
    const float* __restrict__ cb, float* __restrict__ out, int nrows)
{
    extern __shared__ char smc[];
    u64*   finalS = (u64*)(smc);
    float* margS  = (float*)(smc + 512);
    u32*   bestU  = (u32*)(smc + 768);
    u32*   cntS   = (u32*)(smc + 1024);
    u32*   candS  = (u32*)(smc + 1280);
    u32*   zhS    = (u32*)(smc + 9472);
    u32*   chB    = (u32*)(smc + 26880);   // two buffers, CHBYTES each

    const int tid  = threadIdx.x;
    const int wid  = tid >> 5, lane = tid & 31;
    const int g    = lane >> 2, tg = lane & 3;
    const int rbase = blockIdx.x * VROWS;

    // 8 warps = 2 M-groups (32 rows) x 4 N-quarters (32 cols)
    const int mbase = (wid >> 2) * 32;
    const int nq    = (wid & 3) * 32;

    const u32 chBase = smem_u32(chB);

    // prefetch chunk 0 into buffer 0 (cp.async, overlaps with init below)
    {
        const char* src = (const char*)g_ch16;
        #pragma unroll
        for (int t = 0; t < 8; t++) {
            int i = t * VTHR + tid;
            u32 dst = chBase + ((u32)(i >> 4) * APW + (u32)(i & 15) * 4) * 4;
            cp16(dst, src + (size_t)i * 16);
        }
        CP_COMMIT();
    }

    for (int i = tid; i < VROWS; i += VTHR) {
        bestU[i]  = 0xFFFFFFFFu;
        finalS[i] = ~0ull;
        cntS[i]   = 0u;
        margS[i]  = g_zabs[rbase + i] * 4.0e-6f + 4.0e-6f;
    }

    // stage A: zh = fp16(z_e)
    for (int i = tid; i < VROWS * 64; i += VTHR) {
        int r = i >> 6, c = i & 63;
        float2 z = *(const float2*)(g_ze + (size_t)(rbase + r) * DIMC + c * 2);
        __half2 hp(__float2half_rn(z.x), __float2half_rn(z.y));
        zhS[r * APW + c] = *(u32*)&hp;
    }
    CP_WAIT0();
    __syncthreads();

    const int r0 = mbase + g;
    const float mg0 = margS[r0], mg1 = margS[r0 + 8];
    const float mg2 = margS[r0 + 16], mg3 = margS[r0 + 24];

    float dacc[2][4][4];

    for (int q = 0; q < NCHUNK; q++) {
        u32* chD = chB + (u32)(q & 1) * (CHBYTES / 4);

        // prefetch chunk q+1 into the other buffer (overlaps MMA + epilogue)
        if (q < NCHUNK - 1) {
            const char* src = (const char*)(g_ch16 + (size_t)(q + 1) * CHN * DIMC);
            const u32 dstBase = chBase + (u32)((q + 1) & 1) * CHBYTES;
            #pragma unroll
            for (int t = 0; t < 8; t++) {
                int i = t * VTHR + tid;
                u32 dst = dstBase + ((u32)(i >> 4) * APW + (u32)(i & 15) * 4) * 4;
                cp16(dst, src + (size_t)i * 16);
            }
            CP_COMMIT();
        }

        #pragma unroll
        for (int mt = 0; mt < 2; mt++)
            #pragma unroll
            for (int nt = 0; nt < 4; nt++) {
                dacc[mt][nt][0] = 0.f; dacc[mt][nt][1] = 0.f;
                dacc[mt][nt][2] = 0.f; dacc[mt][nt][3] = 0.f;
            }

        #pragma unroll
        for (int kt = 0; kt < 8; kt++) {
            const int ka = kt * 8 + tg;
            u32 a[2][4];
            #pragma unroll
            for (int mt = 0; mt < 2; mt++) {
                const int rb = (mbase + mt * 16 + g) * APW;
                a[mt][0] = zhS[rb + ka];
                a[mt][1] = zhS[rb + 8 * APW + ka];
                a[mt][2] = zhS[rb + ka + 4];
                a[mt][3] = zhS[rb + 8 * APW + ka + 4];
            }
            #pragma unroll
            for (int nt = 0; nt < 4; nt++) {
                const int w = (nq + nt * 8 + g) * APW + ka;
                const u32 b0 = chD[w], b1 = chD[w + 4];
                mma16816(dacc[0][nt], a[0][0], a[0][1], a[0][2], a[0][3], b0, b1);
                mma16816(dacc[1][nt], a[1][0], a[1][1], a[1][2], a[1][3], b0, b1);
            }
        }

        // epilogue: scores + per-row running min
        u32 mn0 = ~0u, mn1 = ~0u, mn2 = ~0u, mn3 = ~0u;
        #pragma unroll
        for (int mt = 0; mt < 2; mt++)
            #pragma unroll
            for (int nt = 0; nt < 4; nt++) {
                const int jb = q * CHN + nq + nt * 8 + 2 * tg;
                const float cn0 = __ldg(g_cnorm + jb);
                const float cn1 = __ldg(g_cnorm + jb + 1);
                float* d = dacc[mt][nt];
                float s0 = fmaf(d[0], -2.0f * DOTSCALE, cn0);
                float s1 = fmaf(d[1], -2.0f * DOTSCALE, cn1);
                float s2 = fmaf(d[2], -2.0f * DOTSCALE, cn0);
                float s3 = fmaf(d[3], -2.0f * DOTSCALE, cn1);
                d[0] = s0; d[1] = s1; d[2] = s2; d[3] = s3;
                u32 ma = min(fmap(s0), fmap(s1));
                u32 mb = min(fmap(s2), fmap(s3));
                if (mt == 0) { mn0 = min(mn0, ma); mn1 = min(mn1, mb); }
                else         { mn2 = min(mn2, ma); mn3 = min(mn3, mb); }
            }
        atomicMin(&bestU[r0],      mn0);
        atomicMin(&bestU[r0 + 8],  mn1);
        atomicMin(&bestU[r0 + 16], mn2);
        atomicMin(&bestU[r0 + 24], mn3);
        __syncthreads();   // mins global; all chD reads complete

        const float t0 = finv(bestU[r0])      + mg0;
        const float t1 = finv(bestU[r0 + 8])  + mg1;
        const float t2 = finv(bestU[r0 + 16]) + mg2;
        const float t3 = finv(bestU[r0 + 24]) + mg3;

        #pragma unroll
        for (int mt = 0; mt < 2; mt++) {
            const int rA = r0 + mt * 16, rB = rA + 8;
            const float tA = mt ? t2 : t0;
            const float tB = mt ? t3 : t1;
            #pragma unroll
            for (int nt = 0; nt < 4; nt++) {
                const int jb = q * CHN + nq + nt * 8 + 2 * tg;
                const float* d = dacc[mt][nt];
                if (d[0] <= tA) {
                    u32 p = atomicAdd(&cntS[rA], 1u);
                    if (p < CAND_MAX) candS[rA * CAND_MAX + p] = (u32)jb;
                }
                if (d[1] <= tA) {
                    u32 p = atomicAdd(&cntS[rA], 1u);
                    if (p < CAND_MAX) candS[rA * CAND_MAX + p] = (u32)(jb + 1);
                }
                if (d[2] <= tB) {
                    u32 p = atomicAdd(&cntS[rB], 1u);
                    if (p < CAND_MAX) candS[rB * CAND_MAX + p] = (u32)jb;
                }
                if (d[3] <= tB) {
                    u32 p = atomicAdd(&cntS[rB], 1u);
                    if (p < CAND_MAX) candS[rB * CAND_MAX + p] = (u32)(jb + 1);
                }
            }
        }

        if (q < NCHUNK - 1) CP_WAIT0();   // next buffer landed
        __syncthreads();
    }

    // exact fp32 refine (reference order); full-scan fallback on overflow
    {
        const int rr = tid >> 2, c4 = tid & 3;
        const float zn = g_znorm[rbase + rr];
        const float* zp = g_ze + (size_t)(rbase + rr) * DIMC;
        int cnt = (int)cntS[rr];
        if (cnt <= CAND_MAX) {
            for (int c = c4; c < cnt; c += 4) {
                int j = (int)candS[rr * CAND_MAX + c];
                const float* cp = cb + (size_t)j * DIMC;
                float dot = 0.f;
                #pragma unroll 8
                for (int d = 0; d < DIMC; d++) dot = fmaf(zp[d], cp[d], dot);
                float dvv = (zn - 2.0f * dot) + __ldg(g_cnorm + j);
                u64 key = ((u64)fmap(dvv) << 32) | (u32)j;
                atomicMin(&finalS[rr], key);
            }
        } else {
            for (int j = c4; j < KC; j += 4) {
                const float* cp = cb + (size_t)j * DIMC;
                float dot = 0.f;
                #pragma unroll 8
                for (int d = 0; d < DIMC; d++) dot = fmaf(zp[d], cp[d], dot);
                float dvv = (zn - 2.0f * dot) + __ldg(g_cnorm + j);
                u64 key = ((u64)fmap(dvv) << 32) | (u32)j;
                atomicMin(&finalS[rr], key);
            }
        }
    }
    __syncthreads();

    if (tid < VROWS) {
        int idx = (int)(finalS[tid] & 0xFFFFFFFFull);
        g_idx[rbase + tid] = idx;
        float* out_id = out + (size_t)nrows * XD + (size_t)nrows * DIMC * 2;
        out_id[rbase + tid] = (float)idx;
    }
}

// ---------------- decoder (fp16 2-term split tensor cores) -------------------
// smem: xh [128][APW]u32 @0 | xl @34816 | wh @69632 | wl @104448 | end 139264
// h2 fp32 [128 col][132 row pitch] aliases @69632
#define DEC_SMEM 139264

__global__ void __launch_bounds__(DTHR, 1) dec_kernel(
    const float* __restrict__ state, const float* __restrict__ cb,
    const float* __restrict__ db1, const float* __restrict__ db2,
    const float* __restrict__ dw3, const float* __restrict__ db3,
    float* __restrict__ out, int nrows)
{
    extern __shared__ char smc[];
    u32* xhS = (u32*)(smc);
    u32* xlS = (u32*)(smc + 34816);
    u32* whS = (u32*)(smc + 69632);
    u32* wlS = (u32*)(smc + 104448);
    float* h2S = (float*)(smc + 69632);     // alias over whS/wlS

    const int tid  = threadIdx.x;
    const int wid  = tid >> 5, lane = tid & 31;
    const int g    = lane >> 2, tg = lane & 3;
    const int rbase = blockIdx.x * DROWS;

    const int mbase = (wid >> 2) * 32;
    const int nq    = (wid & 3) * 32;

    const size_t B = (size_t)nrows;
    float* out_xt = out;
    float* out_zq = out + B * XD + B * (size_t)DIMC;

    float dacc[2][4][4];
    #pragma unroll
    for (int mt = 0; mt < 2; mt++)
        #pragma unroll
        for (int nt = 0; nt < 4; nt++) {
            dacc[mt][nt][0] = 0.f; dacc[mt][nt][1] = 0.f;
            dacc[mt][nt][2] = 0.f; dacc[mt][nt][3] = 0.f;
        }

    // ---- GEMM1: K=384 in 3 chunks of 128 ----
    for (int ch = 0; ch < 3; ch++) {
        if (ch < 2) {
            for (int i = tid; i < DROWS * 64; i += DTHR) {
                int r = i >> 6, cw = i & 63;
                float2 v = *(const float2*)(state + (size_t)(rbase + r) * SDIM + ch * 128 + 2 * cw);
                float v0 = v.x * 16.0f, v1 = v.y * 16.0f;
                __half h0 = __float2half_rn(v0), h1 = __float2half_rn(v1);
                __half l0 = __float2half_rn(v0 - __half2float(h0));
                __half l1 = __float2half_rn(v1 - __half2float(h1));
                __half2 hp(h0, h1), lp(l0, l1);
                xhS[r * APW + cw] = *(u32*)&hp;
                xlS[r * APW + cw] = *(u32*)&lp;
            }
        } else {
            for (int i = tid; i < DROWS * 64; i += DTHR) {
                int r = i >> 6, cw = i & 63;
                int d = 2 * cw;
                float2 z = *(const float2*)(g_ze + (size_t)(rbase + r) * DIMC + d);
                int idx = g_idx[rbase + r];
                float2 q = *(const float2*)(cb + (size_t)idx * DIMC + d);
                *(float2*)(out_zq + (size_t)(rbase + r) * DIMC + d) = q;
                float v0 = (z.x + (q.x - z.x)) * 16.0f;
                float v1 = (z.y + (q.y - z.y)) * 16.0f;
                __half h0 = __float2half_rn(v0), h1 = __float2half_rn(v1);
                __half l0 = __float2half_rn(v0 - __half2float(h0));
                __half l1 = __float2half_rn(v1 - __half2float(h1));
                __half2 hp(h0, h1), lp(l0, l1);
                xhS[r * APW + cw] = *(u32*)&hp;
                xlS[r * APW + cw] = *(u32*)&lp;
            }
        }
        {
            const u32* srcH = (const u32*)g_w1h;
            const u32* srcL = (const u32*)g_w1l;
            for (int i = tid; i < 128 * 64; i += DTHR) {
                int n = i >> 6, cw = i & 63;
                int woff = n * 192 + ch * 64 + cw;
                whS[n * APW + cw] = srcH[woff];
                wlS[n * APW + cw] = srcL[woff];
            }
        }
        __syncthreads();

        #pragma unroll
        for (int kt = 0; kt < 8; kt++) {
            const int ka = kt * 8 + tg;
            u32 ah[2][4], al[2][4];
            #pragma unroll
            for (int mt = 0; mt < 2; mt++) {
                const int rb = (mbase + mt * 16 + g) * APW;
                ah[mt][0] = xhS[rb + ka];
                ah[mt][1] = xhS[rb + 8 * APW + ka];
                ah[mt][2] = xhS[rb + ka + 4];
                ah[mt][3] = xhS[rb + 8 * APW + ka + 4];
                al[mt][0] = xlS[rb + ka];
                al[mt][1] = xlS[rb + 8 * APW + ka];
                al[mt][2] = xlS[rb + ka + 4];
                al[mt][3] = xlS[rb + 8 * APW + ka + 4];
            }
            #pragma unroll
            for (int nt = 0; nt < 4; nt++) {
                const int w = (nq + nt * 8 + g) * APW + ka;
                const u32 bh0 = whS[w], bh1 = whS[w + 4];
                const u32 bl0 = wlS[w], bl1 = wlS[w + 4];
                #pragma unroll
                for (int mt = 0; mt < 2; mt++) {
                    mma16816(dacc[mt][nt], ah[mt][0], ah[mt][1], ah[mt][2], ah[mt][3], bh0, bh1);
                    mma16816(dacc[mt][nt], al[mt][0], al[mt][1], al[mt][2], al[mt][3], bh0, bh1);
                    mma16816(dacc[mt][nt], ah[mt][0], ah[mt][1], ah[mt][2], ah[mt][3], bl0, bl1);
                }
            }
        }
        __syncthreads();
    }

    // ---- GEMM1 epilogue: h1 = relu(acc/1024 + b1); restage (x16 split) ----
    #pragma unroll
    for (int mt = 0; mt < 2; mt++) {
        const int rA = mbase + mt * 16 + g, rB = rA + 8;
        #pragma unroll
        for (int nt = 0; nt < 4; nt++) {
            const int jb = nq + nt * 8 + 2 * tg;
            const float b0v = __ldg(db1 + jb), b1v = __ldg(db1 + jb + 1);
            float* d = dacc[mt][nt];
            float s0 = fmaxf(fmaf(d[0], DOTSCALE, b0v), 0.f) * 16.0f;
            float s1 = fmaxf(fmaf(d[1], DOTSCALE, b1v), 0.f) * 16.0f;
            float s2 = fmaxf(fmaf(d[2], DOTSCALE, b0v), 0.f) * 16.0f;
            float s3 = fmaxf(fmaf(d[3], DOTSCALE, b1v), 0.f) * 16.0f;
            const int w = (nq >> 1) + nt * 4 + tg;
            __half h0 = __float2half_rn(s0), h1 = __float2half_rn(s1);
            __half l0 = __float2half_rn(s0 - __half2float(h0));
            __half l1 = __float2half_rn(s1 - __half2float(h1));
            __half2 hpA(h0, h1), lpA(l0, l1);
            xhS[rA * APW + w] = *(u32*)&hpA;
            xlS[rA * APW + w] = *(u32*)&lpA;
            __half h2 = __float2half_rn(s2), h3 = __float2half_rn(s3);
            __half l2 = __float2half_rn(s2 - __half2float(h2));
            __half l3 = __float2half_rn(s3 - __half2float(h3));
            __half2 hpB(h2, h3), lpB(l2, l3);
            xhS[rB * APW + w] = *(u32*)&hpB;
            xlS[rB * APW + w] = *(u32*)&lpB;
        }
    }
    {
        const u32* srcH = (const u32*)g_w2h;
        const u32* srcL = (const u32*)g_w2l;
        for (int i = tid; i < 128 * 64; i += DTHR) {
            int n = i >> 6, cw = i & 63;
            whS[n * APW + cw] = srcH[n * 64 + cw];
            wlS[n * APW + cw] = srcL[n * 64 + cw];
        }
    }
    __syncthreads();

    // ---- GEMM2: K=128 ----
    #pragma unroll
    for (int mt = 0; mt < 2; mt++)
        #pragma unroll
        for (int nt = 0; nt < 4; nt++) {
            dacc[mt][nt][0] = 0.f; dacc[mt][nt][1] = 0.f;
            dacc[mt][nt][2] = 0.f; dacc[mt][nt][3] = 0.f;
        }
    #pragma unroll
    for (int kt = 0; kt < 8; kt++) {
        const int ka = kt * 8 + tg;
        u32 ah[2][4], al[2][4];
        #pragma unroll
        for (int mt = 0; mt < 2; mt++) {
            const int rb = (mbase + mt * 16 + g) * APW;
            ah[mt][0] = xhS[rb + ka];
            ah[mt][1] = xhS[rb + 8 * APW + ka];
            ah[mt][2] = xhS[rb + ka + 4];
            ah[mt][3] = xhS[rb + 8 * APW + ka + 4];
            al[mt][0] = xlS[rb + ka];
            al[mt][1] = xlS[rb + 8 * APW + ka];
            al[mt][2] = xlS[rb + ka + 4];
            al[mt][3] = xlS[rb + 8 * APW + ka + 4];
        }
        #pragma unroll
        for (int nt = 0; nt < 4; nt++) {
            const int w = (nq + nt * 8 + g) * APW + ka;
            const u32 bh0 = whS[w], bh1 = whS[w + 4];
            const u32 bl0 = wlS[w], bl1 = wlS[w + 4];
            #pragma unroll
            for (int mt = 0; mt < 2; mt++) {
                mma16816(dacc[mt][nt], ah[mt][0], ah[mt][1], ah[mt][2], ah[mt][3], bh0, bh1);
                mma16816(dacc[mt][nt], al[mt][0], al[mt][1], al[mt][2], al[mt][3], bh0, bh1);
                mma16816(dacc[mt][nt], ah[mt][0], ah[mt][1], ah[mt][2], ah[mt][3], bl0, bl1);
            }
        }
    }
    __syncthreads();   // wh/wl reads done before h2 alias-write

    // ---- GEMM2 epilogue: h2 fp32 -> smem [col][row pitch 132] ----
    #pragma unroll
    for (int mt = 0; mt < 2; mt++) {
        const int rA = mbase + mt * 16 + g, rB = rA + 8;
        #pragma unroll
        for (int nt = 0; nt < 4; nt++) {
            const int jb = nq + nt * 8 + 2 * tg;
            const float b0v = __ldg(db2 + jb), b1v = __ldg(db2 + jb + 1);
            float* d = dacc[mt][nt];
            h2S[jb * 132 + rA]       = fmaxf(fmaf(d[0], DOTSCALE, b0v), 0.f);
            h2S[(jb + 1) * 132 + rA] = fmaxf(fmaf(d[1], DOTSCALE, b1v), 0.f);
            h2S[jb * 132 + rB]       = fmaxf(fmaf(d[2], DOTSCALE, b0v), 0.f);
            h2S[(jb + 1) * 132 + rB] = fmaxf(fmaf(d[3], DOTSCALE, b1v), 0.f);
        }
    }
    __syncthreads();

    // ---- final layer: fp32 scalar, 8 cols ----
    {
        int r = tid & 127;
        int c = (tid >> 7) * 2;
        float a0 = 0.f, a1 = 0.f;
        #pragma unroll 4
        for (int d = 0; d < DIMC; d++) {
            float h = h2S[d * 132 + r];
            a0 = fmaf(h, dw3[d * XD + c],     a0);
            a1 = fmaf(h, dw3[d * XD + c + 1], a1);
        }
        out_xt[(size_t)(rbase + r) * XD + c]     = a0 + db3[c];
        out_xt[(size_t)(rbase + r) * XD + c + 1] = a1 + db3[c + 1];
    }
}

// ---------------- launch ----------------
extern "C" void kernel_launch(void* const* d_in, const int* in_sizes, int n_in,
                              void* d_out, int out_size) {
    const float* state = (const float*)d_in[0];
    const float* x     = (const float*)d_in[1];
    const float* cb    = (const float*)d_in[2];
    const float* ew1   = (const float*)d_in[3];
    const float* eb1   = (const float*)d_in[4];
    const float* ew2   = (const float*)d_in[5];
    const float* eb2   = (const float*)d_in[6];
    const float* ew3   = (const float*)d_in[7];
    const float* eb3   = (const float*)d_in[8];
    const float* dw1   = (const float*)d_in[9];
    const float* db1   = (const float*)d_in[10];
    const float* dw2   = (const float*)d_in[11];
    const float* db2   = (const float*)d_in[12];
    const float* dw3   = (const float*)d_in[13];
    const float* db3   = (const float*)d_in[14];

    const int nrows = in_sizes[0] / SDIM;   // 262144

    size_t smemA = (size_t)(136 + 128) * PITCH * sizeof(float);   // 71808
    static bool attrs_set = false;
    if (!attrs_set) {
        cudaFuncSetAttribute((const void*)enc_kernel, cudaFuncAttributeMaxDynamicSharedMemorySize, (int)smemA);
        cudaFuncSetAttribute((const void*)vq_kernel,  cudaFuncAttributeMaxDynamicSharedMemorySize, VQ_SMEM);
        cudaFuncSetAttribute((const void*)dec_kernel, cudaFuncAttributeMaxDynamicSharedMemorySize, DEC_SMEM);
        attrs_set = true;
    }

    vq_prep<<<KC, DIMC>>>(cb);
    dec_prep<<<(128 * 384 + 128 * 128 + 255) / 256, 256>>>(dw1, dw2);
    enc_kernel<<<nrows / ROWS, NTHR, smemA>>>(state, x, ew1, eb1, ew2, eb2, ew3, eb3,
                                              (float*)d_out, nrows);
    vq_kernel<<<nrows / VROWS, VTHR, VQ_SMEM>>>(cb, (float*)d_out, nrows);
    dec_kernel<<<nrows / DROWS, DTHR, DEC_SMEM>>>(state, cb, db1, db2, dw3, db3,
                                                  (float*)d_out, nrows);
}